// round 1
// baseline (speedup 1.0000x reference)
#include <cuda_runtime.h>
#include <math.h>

#define EPSF 1e-9f
#define LN10F 2.302585092994046f

// per-position results: 32 act + 576 miu = 608 floats, 1024 positions
__device__ float g_scratch[1024 * 608];

struct SMem {
    float pose[32 * 16];    // input poses
    float act[32];          // input activations
    float votes[32*32*18];  // [ci][co][18]
    float r[32 * 32];       // routing weights [ci][co]
    float S[32 * 32];       // per (i,c) sum of log_p over ch
    float m[32 * 32];       // per (i,c) max of log_p over ch
    float miu[32 * 18];     // [co][18]
    float sigma[32 * 18];   // [co][18] (includes +EPS)
    float A[32 * 18];       // -0.5*log(sigma)
    float Binv[32 * 18];    // 0.5/sigma
    float rowsum[32];       // per-i sums
    float rs[32];           // r_sum per co
    float maxlp[32];        // per-i max log_p
    float actout[32];       // output activations
};

__global__ __launch_bounds__(256, 2)
void capsule_kernel(const float* __restrict__ x,
                    const float* __restrict__ w,
                    const float* __restrict__ beta_v,
                    const float* __restrict__ beta_a,
                    const float* __restrict__ coord) {
    extern __shared__ SMem smem_raw[];
    SMem& s = smem_raw[0];
    const int n   = blockIdx.x;     // 0..1023, n = ((b*8+i)*8+j)
    const int tid = threadIdx.x;    // 256 threads
    const int sp  = n & 63;         // spatial index i*8+j

    // ---- load x row: 32 capsules x (16 pose + 1 act) ----
    const float* xr = x + (size_t)n * 544;
    for (int k = tid; k < 544; k += 256) {
        int cap = k / 17, rr = k - cap * 17;
        float v = xr[k];
        if (rr == 16) s.act[cap] = v;
        else          s.pose[cap * 16 + rr] = v;
    }
    const float c0 = coord[sp * 2 + 0];
    const float c1 = coord[sp * 2 + 1];
    __syncthreads();

    // ---- votes: votes[i][c][2 + a*4+d] = sum_b pose[i][a*4+b] * w[i][c][b*4+d] ----
    for (int pair = tid; pair < 1024; pair += 256) {
        int i = pair >> 5;
        const float4* wp = reinterpret_cast<const float4*>(w + (size_t)pair * 16);
        float4 w0 = wp[0], w1 = wp[1], w2 = wp[2], w3 = wp[3];
        float* vd = s.votes + pair * 18;
        vd[0] = c0; vd[1] = c1;
        const float* pr = s.pose + i * 16;
        #pragma unroll
        for (int a = 0; a < 4; a++) {
            float p0 = pr[a*4+0], p1 = pr[a*4+1], p2 = pr[a*4+2], p3 = pr[a*4+3];
            vd[2 + a*4 + 0] = p0*w0.x + p1*w1.x + p2*w2.x + p3*w3.x;
            vd[2 + a*4 + 1] = p0*w0.y + p1*w1.y + p2*w2.y + p3*w3.y;
            vd[2 + a*4 + 2] = p0*w0.z + p1*w1.z + p2*w2.z + p3*w3.z;
            vd[2 + a*4 + 3] = p0*w0.w + p1*w1.w + p2*w2.w + p3*w3.w;
        }
        s.r[pair] = 1.0f / 32.0f;   // r init
    }
    __syncthreads();

    // ---- EM routing, 3 iterations ----
    for (int it = 0; it < 3; ++it) {
        if (it > 0) {
            // E-step: precompute A, Binv per (c,h)
            for (int u = tid; u < 576; u += 256) {
                float sg = s.sigma[u];
                s.A[u]    = -0.5f * logf(sg);
                s.Binv[u] = 0.5f / sg;
            }
            __syncthreads();
            // per (i,c): sum and max of log_p over ch
            for (int idx = tid; idx < 1024; idx += 256) {
                int c = idx & 31;
                const float* vv = s.votes + idx * 18;
                const float* Ac = s.A    + c * 18;
                const float* Bc = s.Binv + c * 18;
                const float* mc = s.miu  + c * 18;
                float Ssum = 0.f, mx = -INFINITY;
                #pragma unroll
                for (int h = 0; h < 18; ++h) {
                    float d  = vv[h] - mc[h];
                    float lp = Ac[h] - d * d * Bc[h];
                    Ssum += lp;
                    mx = fmaxf(mx, lp);
                }
                s.S[idx] = Ssum;
                s.m[idx] = mx;
            }
            __syncthreads();
            // max over (c,h) per i   (bank-skewed)
            if (tid < 32) {
                float mx = -INFINITY;
                for (int cc = 0; cc < 32; ++cc) {
                    int c = (cc + tid) & 31;
                    mx = fmaxf(mx, s.m[tid * 32 + c]);
                }
                s.maxlp[tid] = mx;
            }
            __syncthreads();
            // p = exp(S - 18*(max - ln10)); ap = p * act_out[c]
            for (int idx = tid; idx < 1024; idx += 256) {
                int i = idx >> 5, c = idx & 31;
                float p = expf(s.S[idx] - 18.0f * (s.maxlp[i] - LN10F));
                s.r[idx] = p * s.actout[c];
            }
            __syncthreads();
            // r = ap / (sum_c ap + EPS)   (bank-skewed rowsum)
            if (tid < 32) {
                float sum = 0.f;
                for (int cc = 0; cc < 32; ++cc) {
                    int c = (cc + tid) & 31;
                    sum += s.r[tid * 32 + c];
                }
                s.rowsum[tid] = sum;
            }
            __syncthreads();
            for (int idx = tid; idx < 1024; idx += 256)
                s.r[idx] = s.r[idx] / (s.rowsum[idx >> 5] + EPSF);
            __syncthreads();
        }

        // ---- M-step ----
        // r *= act[i]
        for (int idx = tid; idx < 1024; idx += 256)
            s.r[idx] *= s.act[idx >> 5];
        __syncthreads();
        // r /= (sum_c r + EPS)
        if (tid < 32) {
            float sum = 0.f;
            for (int cc = 0; cc < 32; ++cc) {
                int c = (cc + tid) & 31;
                sum += s.r[tid * 32 + c];
            }
            s.rowsum[tid] = sum;
        }
        __syncthreads();
        for (int idx = tid; idx < 1024; idx += 256)
            s.r[idx] = s.r[idx] / (s.rowsum[idx >> 5] + EPSF);
        __syncthreads();
        // r_sum[c] = sum_i r   (conflict-free: consecutive tid -> consecutive addr)
        if (tid < 32) {
            float sum = 0.f;
            for (int i = 0; i < 32; ++i) sum += s.r[i * 32 + tid];
            s.rs[tid] = sum;
        }
        __syncthreads();
        // r1 = r / (r_sum + EPS)  (overwrite r)
        for (int idx = tid; idx < 1024; idx += 256)
            s.r[idx] = s.r[idx] / (s.rs[idx & 31] + EPSF);
        __syncthreads();
        // miu[c][h] = sum_i votes[i][c][h] * r1[i][c]
        for (int u = tid; u < 576; u += 256) {
            int c = u / 18, h = u - c * 18;
            float acc = 0.f;
            for (int i = 0; i < 32; ++i)
                acc += s.votes[(i * 32 + c) * 18 + h] * s.r[i * 32 + c];
            s.miu[u] = acc;
        }
        __syncthreads();
        // sigma[c][h] = sum_i (v - miu)^2 * r1 + EPS
        for (int u = tid; u < 576; u += 256) {
            int c = u / 18, h = u - c * 18;
            float mu = s.miu[u];
            float acc = 0.f;
            for (int i = 0; i < 32; ++i) {
                float d = s.votes[(i * 32 + c) * 18 + h] - mu;
                acc += d * d * s.r[i * 32 + c];
            }
            s.sigma[u] = acc + EPSF;
        }
        __syncthreads();

        // ---- activation update ----
        if (it < 2) {
            if (tid < 32) {  // softmax over co of r_sum
                float v = s.rs[tid];
                float mx = v;
                #pragma unroll
                for (int o = 16; o > 0; o >>= 1)
                    mx = fmaxf(mx, __shfl_xor_sync(0xffffffffu, mx, o));
                float e = expf(v - mx);
                float ssum = e;
                #pragma unroll
                for (int o = 16; o > 0; o >>= 1)
                    ssum += __shfl_xor_sync(0xffffffffu, ssum, o);
                s.actout[tid] = e / ssum;
            }
        } else {
            if (tid < 32) {  // final: softmax(0.03 * (beta_a - sum_h cost_h))
                float cost = 0.f;
                for (int h = 0; h < 18; ++h)
                    cost += beta_v[tid * 18 + h] + 0.5f * logf(s.sigma[tid * 18 + h]);
                cost *= s.rs[tid];
                float logit = 0.03f * (beta_a[tid] - cost);
                float mx = logit;
                #pragma unroll
                for (int o = 16; o > 0; o >>= 1)
                    mx = fmaxf(mx, __shfl_xor_sync(0xffffffffu, mx, o));
                float e = expf(logit - mx);
                float ssum = e;
                #pragma unroll
                for (int o = 16; o > 0; o >>= 1)
                    ssum += __shfl_xor_sync(0xffffffffu, ssum, o);
                s.actout[tid] = e / ssum;
            }
        }
        __syncthreads();
    }

    // ---- write per-position results to scratch ----
    float* outp = g_scratch + (size_t)n * 608;
    if (tid < 32) outp[tid] = s.actout[tid];
    for (int u = tid; u < 576; u += 256) outp[32 + u] = s.miu[u];
}

// spatial mean over the 64 positions per batch element
__global__ void reduce_kernel(float* __restrict__ out) {
    int t = blockIdx.x * blockDim.x + threadIdx.x;
    if (t >= 16 * 608) return;
    int b = t / 608, k = t - b * 608;
    const float* base = g_scratch + (size_t)(b * 64) * 608 + k;
    float sum = 0.f;
    #pragma unroll 4
    for (int sp = 0; sp < 64; ++sp) sum += base[sp * 608];
    sum *= (1.0f / 64.0f);
    if (k < 32) out[b * 32 + k] = sum;                 // outputs [16,32]
    else        out[512 + b * 576 + (k - 32)] = sum;   // pose_out [16,32,18]
}

extern "C" void kernel_launch(void* const* d_in, const int* in_sizes, int n_in,
                              void* d_out, int out_size) {
    const float* x      = (const float*)d_in[0];
    const float* w      = (const float*)d_in[1];
    const float* beta_v = (const float*)d_in[2];
    const float* beta_a = (const float*)d_in[3];
    const float* coord  = (const float*)d_in[4];
    float* out = (float*)d_out;

    size_t smem = sizeof(SMem);
    cudaFuncSetAttribute(capsule_kernel,
                         cudaFuncAttributeMaxDynamicSharedMemorySize, (int)smem);
    capsule_kernel<<<1024, 256, smem>>>(x, w, beta_v, beta_a, coord);
    reduce_kernel<<<(16 * 608 + 255) / 256, 256>>>(out);
}